// round 2
// baseline (speedup 1.0000x reference)
#include <cuda_runtime.h>

#define B_    4
#define C_    64
#define H_    128
#define W_    256
#define P_    32768      // H_*W_ pixels per batch
#define NC_   19
#define EPS_  1e-5f

#define TILE_ 2048
#define THR_  256
#define RPT_  8          // TILE_/THR_
#define CHG_  8          // channels per stats block

// ---- device scratch (static allocation only, per harness rules) ----
__device__ unsigned char g_gtr[B_ * P_];        // subsampled class map (128 KB)
__device__ float  g_sum[NC_ * B_ * C_];
__device__ float  g_sq [NC_ * B_ * C_];
__device__ int    g_cnt[NC_ * B_];
__device__ float2 g_sb [NC_ * B_ * C_];         // {scale, bias}

// ---------------- kernel 0: subsample gt (stride 4) + zero accumulators ----
__global__ void __launch_bounds__(256) k_prep(const int* __restrict__ gt) {
    int i = blockIdx.x * 256 + threadIdx.x;     // 0 .. 131071
    int r = i & (P_ - 1);
    int h = r >> 8;
    int w = r & 255;
    int b = i >> 15;
    // gt index: b*512*1024 + (4h)*1024 + 4w
    g_gtr[i] = (unsigned char)__ldg(&gt[(b << 19) + (h << 12) + (w << 2)]);
    if (i < NC_ * B_ * C_) { g_sum[i] = 0.f; g_sq[i] = 0.f; }
    if (i < NC_ * B_)      { g_cnt[i] = 0; }
}

// ---------------- kernel 1: per-class stats via tile-local counting sort ----
// Block = (batch, pixel tile of 2048, group of 8 channels). The class sort is
// channel-independent: do it once, reuse sorted order for all 8 channels.
// Sorted order => contiguous same-class runs per lane => ~1 atomic flush per
// 8 elements instead of per-element atomics.
__global__ void __launch_bounds__(THR_) k_stats(const float* __restrict__ x) {
    __shared__ float    s_vals[2][TILE_];
    __shared__ unsigned s_order[TILE_];          // (class<<16) | local pixel
    __shared__ int      s_cnt[NC_];
    __shared__ int      s_cur[NC_];

    const int tid  = threadIdx.x;
    const int bid  = blockIdx.x;                 // 512 blocks = 4b * 16tiles * 8chg
    const int b    = bid >> 7;
    const int tile = (bid >> 3) & 15;
    const int cg   = bid & 7;
    const int ch0  = cg * CHG_;
    const int gbase = b * P_ + tile * TILE_;

    if (tid < NC_) s_cnt[tid] = 0;
    __syncthreads();

    // count
    int cls[RPT_];
#pragma unroll
    for (int k = 0; k < RPT_; ++k) {
        int p = tid + k * THR_;
        int c = g_gtr[gbase + p];
        cls[k] = c;
        atomicAdd(&s_cnt[c], 1);
    }
    __syncthreads();

    // exclusive prefix (19 entries, single thread) + global pixel counts (once per tile)
    if (tid == 0) {
        int acc = 0;
#pragma unroll
        for (int i = 0; i < NC_; ++i) { int n = s_cnt[i]; s_cur[i] = acc; acc += n; }
    }
    if (cg == 0 && tid < NC_) atomicAdd(&g_cnt[tid * B_ + b], s_cnt[tid]);
    __syncthreads();

    // scatter: build sorted order
#pragma unroll
    for (int k = 0; k < RPT_; ++k) {
        int p = tid + k * THR_;
        int pos = atomicAdd(&s_cur[cls[k]], 1);
        s_order[pos] = ((unsigned)cls[k] << 16) | (unsigned)p;
    }
    __syncthreads();

    // each thread caches its 8 contiguous sorted slots in registers
    int myc[RPT_], myp[RPT_];
#pragma unroll
    for (int k = 0; k < RPT_; ++k) {
        unsigned o = s_order[tid * RPT_ + k];
        myc[k] = (int)(o >> 16);
        myp[k] = (int)(o & 0xffffu);
    }

    // preload first channel tile (coalesced float4)
    {
        const float4* xp = (const float4*)(x + ((size_t)(b * C_ + ch0)) * P_ + tile * TILE_);
        ((float4*)s_vals[0])[tid]        = xp[tid];
        ((float4*)s_vals[0])[THR_ + tid] = xp[THR_ + tid];
    }

    for (int cc = 0; cc < CHG_; ++cc) {
        __syncthreads();
        // prefetch next channel into the other buffer
        if (cc + 1 < CHG_) {
            const float4* xp = (const float4*)(x + ((size_t)(b * C_ + ch0 + cc + 1)) * P_ + tile * TILE_);
            int nb = (cc + 1) & 1;
            ((float4*)s_vals[nb])[tid]        = xp[tid];
            ((float4*)s_vals[nb])[THR_ + tid] = xp[THR_ + tid];
        }
        const int ch  = ch0 + cc;
        const int buf = cc & 1;

        // run-deferred accumulation over sorted slots
        int   cur = myc[0];
        float rs = 0.f, rq = 0.f;
#pragma unroll
        for (int k = 0; k < RPT_; ++k) {
            float v = s_vals[buf][myp[k]];
            if (myc[k] != cur) {
                int idx = (cur * B_ + b) * C_ + ch;
                atomicAdd(&g_sum[idx], rs);
                atomicAdd(&g_sq[idx],  rq);
                cur = myc[k];
                rs = v; rq = v * v;
            } else {
                rs += v;
                rq = fmaf(v, v, rq);
            }
        }
        int idx = (cur * B_ + b) * C_ + ch;
        atomicAdd(&g_sum[idx], rs);
        atomicAdd(&g_sq[idx],  rq);
    }
}

// ---------------- kernel 2: finalize per-(c,b,ch) affine params -------------
__global__ void __launch_bounds__(C_) k_finalize(const float* __restrict__ emu,
                                                 const float* __restrict__ estd) {
    const int c  = blockIdx.x;     // 0..18
    const int ch = threadIdx.x;    // 0..63

    float mean[B_], sd[B_];
#pragma unroll
    for (int b = 0; b < B_; ++b) {
        int   n   = g_cnt[c * B_ + b];
        float fn  = (n > 0) ? (float)n : 1.f;
        int   idx = (c * B_ + b) * C_ + ch;
        float m   = g_sum[idx] / fn;
        float q   = g_sq[idx]  / fn;
        float var = fmaxf(q - m * m, 0.f);
        mean[b] = m;
        sd[b]   = sqrtf(var + EPS_);
    }
    float am = 0.25f * (mean[0] + mean[1] + mean[2] + mean[3]);
    float as = 0.25f * (sd[0] + sd[1] + sd[2] + sd[3]);
    float vm = 0.f, vs = 0.f;
#pragma unroll
    for (int b = 0; b < B_; ++b) {
        vm += (mean[b] - am) * (mean[b] - am);
        vs += (sd[b]   - as) * (sd[b]   - as);
    }
    vm *= (1.f / 3.f);   // ddof = 1, B = 4
    vs *= (1.f / 3.f);
    float sqm = sqrtf(vm + EPS_);
    float sqs = sqrtf(vs + EPS_);

#pragma unroll
    for (int b = 0; b < B_; ++b) {
        int   idx   = (c * B_ + b) * C_ + ch;
        float beta  = mean[b] + emu[idx]  * sqm;
        float gamma = sd[b]   + estd[idx] * sqs;
        float sc    = gamma / sd[b];
        g_sb[idx] = make_float2(sc, beta - mean[b] * sc);
    }
}

// ---------------- kernel 3: apply out = x*scale[c] + bias[c] ----------------
__global__ void __launch_bounds__(256) k_apply(const float* __restrict__ x,
                                               float* __restrict__ out) {
    __shared__ float2 tab[NC_];
    const int bid = blockIdx.x;          // 4096 = (4b*64ch)*16 splits
    const int s   = bid & 15;
    const int bc  = bid >> 4;
    const int ch  = bc & 63;
    const int b   = bc >> 6;
    const int tid = threadIdx.x;

    if (tid < NC_) tab[tid] = g_sb[(tid * B_ + b) * C_ + ch];
    __syncthreads();

    const size_t base = ((size_t)(b * C_ + ch)) * P_ + s * TILE_;
    const float4*   xp = (const float4*)(x + base);
    float4*         op = (float4*)(out + base);
    const unsigned* gp = (const unsigned*)(g_gtr + b * P_ + s * TILE_);

#pragma unroll
    for (int j = 0; j < 2; ++j) {
        int i = tid + j * 256;
        float4   v = xp[i];
        unsigned u = gp[i];
        float2 s0 = tab[u & 255u];
        float2 s1 = tab[(u >> 8) & 255u];
        float2 s2 = tab[(u >> 16) & 255u];
        float2 s3 = tab[u >> 24];
        float4 r;
        r.x = fmaf(v.x, s0.x, s0.y);
        r.y = fmaf(v.y, s1.x, s1.y);
        r.z = fmaf(v.z, s2.x, s2.y);
        r.w = fmaf(v.w, s3.x, s3.y);
        op[i] = r;
    }
}

// ---------------- launch -----------------------------------------------------
extern "C" void kernel_launch(void* const* d_in, const int* in_sizes, int n_in,
                              void* d_out, int out_size) {
    const float* x    = (const float*)d_in[0];
    const int*   gt   = (const int*)  d_in[1];
    const float* emu  = (const float*)d_in[2];
    const float* estd = (const float*)d_in[3];
    float*       out  = (float*)d_out;

    k_prep    <<<512, 256>>>(gt);
    k_stats   <<<512, THR_>>>(x);
    k_finalize<<<NC_, C_>>>(emu, estd);
    k_apply   <<<4096, 256>>>(x, out);
}

// round 3
// speedup vs baseline: 1.9433x; 1.9433x over previous
#include <cuda_runtime.h>

#define B_    4
#define C_    64
#define P_    32768      // 128*256 pixels per batch
#define NC_   19
#define EPS_  1e-5f

// ---- stats kernel config ----
#define ST_TILE  1024
#define ST_THR   256
#define ST_RPT   4           // ST_TILE / ST_THR
#define ST_CHG   16          // channels per block
#define ST_TILES 32          // P_ / ST_TILE

// ---- device scratch ----
__device__ unsigned char g_gtr[B_ * P_];        // subsampled class map (128 KB)
__device__ float  g_sum[NC_ * B_ * C_];
__device__ float  g_sq [NC_ * B_ * C_];
__device__ int    g_cnt[NC_ * B_];
__device__ float2 g_sb [NC_ * B_ * C_];         // {scale, bias}

// =============== kernel 1: stats (inline gt subsample + counting sort) ======
// Block = (b, pixel tile of 1024, group of 16 channels). Sort once per block,
// reuse sorted order for 16 channels. All flushes are predicated @P REDG
// (single-statement ifs) — no divergent branch regions in the hot loop.
__global__ void __launch_bounds__(ST_THR) k_stats(const float* __restrict__ x,
                                                  const int*   __restrict__ gt) {
    __shared__ float          s_vals[2][ST_TILE];
    __shared__ unsigned short s_order[ST_TILE];      // (class<<10) | local pixel
    __shared__ int            s_cnt[NC_];
    __shared__ int            s_cur[NC_];

    const int tid  = threadIdx.x;
    const int bid  = blockIdx.x;                     // 512 = b(4) * tile(32) * cg(4)
    const int b    = bid >> 7;
    const int tile = (bid >> 2) & 31;
    const int cg   = bid & 3;
    const int ch0  = cg * ST_CHG;
    const int lane = tid & 31;

    if (tid < NC_) s_cnt[tid] = 0;
    __syncthreads();

    // --- classify pixels of this tile (subsample gt on the fly) ---
    int cls[ST_RPT];
#pragma unroll
    for (int k = 0; k < ST_RPT; ++k) {
        int lp = tid + k * ST_THR;
        int p  = tile * ST_TILE + lp;
        int h  = p >> 8, w = p & 255;
        int c  = gt[(b << 19) + (h << 12) + (w << 2)];
        cls[k] = c;
        atomicAdd(&s_cnt[c], 1);
        if (cg == 0) g_gtr[b * P_ + p] = (unsigned char)c;   // for k_apply
    }
    __syncthreads();

    if (tid == 0) {
        int a = 0;
#pragma unroll
        for (int i = 0; i < NC_; ++i) { int n = s_cnt[i]; s_cur[i] = a; a += n; }
    }
    if (cg == 0 && tid < NC_) atomicAdd(&g_cnt[tid * B_ + b], s_cnt[tid]);
    __syncthreads();

    // --- scatter: build sorted order (ushort: class<<10 | local pixel) ---
#pragma unroll
    for (int k = 0; k < ST_RPT; ++k) {
        int lp  = tid + k * ST_THR;
        int pos = atomicAdd(&s_cur[cls[k]], 1);
        s_order[pos] = (unsigned short)((cls[k] << 10) | lp);
    }
    __syncthreads();

    // --- each thread caches its 4 contiguous sorted slots ---
    ushort4 o4 = ((const ushort4*)s_order)[tid];
    const int c0 = o4.x >> 10, c1 = o4.y >> 10, c2 = o4.z >> 10, c3 = o4.w >> 10;
    const int p0 = o4.x & 1023, p1 = o4.y & 1023, p2 = o4.z & 1023, p3 = o4.w & 1023;

    // membership predicates (hoisted out of channel loop)
    const bool e23   = (c2 == c3);
    const bool e123  = e23 && (c1 == c2);
    const bool e0123 = e123 && (c0 == c1);
    const bool h1    = (c1 == c0);
    const bool h2    = (c2 == c0);
    const bool headp = (c0 != c3);
    const bool m1p   = (c1 != c0) && (c1 != c3);
    const bool m2p   = (c2 != c0) && (c2 != c3);

    // preload channel 0 tile
    const float* xb0 = x + ((size_t)(b * C_ + ch0)) * P_ + tile * ST_TILE;
    ((float4*)s_vals[0])[tid] = ((const float4*)xb0)[tid];
    __syncthreads();

    for (int cc = 0; cc < ST_CHG; ++cc) {
        const int buf = cc & 1;
        float4 nv;
        const bool more = (cc + 1 < ST_CHG);
        if (more) {   // uniform branch; LDG issued early to hide latency
            const float* xbn = x + ((size_t)(b * C_ + ch0 + cc + 1)) * P_ + tile * ST_TILE;
            nv = ((const float4*)xbn)[tid];
        }

        const float v0 = s_vals[buf][p0];
        const float v1 = s_vals[buf][p1];
        const float v2 = s_vals[buf][p2];
        const float v3 = s_vals[buf][p3];

        const int base = b * C_ + ch0 + cc;   // idx(c) = c*(B_*C_) + base

        // trailing run (class c3) — select-based, branch-free
        float rs = v3 + (e23 ? v2 : 0.f) + (e123 ? v1 : 0.f) + (e0123 ? v0 : 0.f);
        float rq = v3 * v3 + (e23 ? v2 * v2 : 0.f) + (e123 ? v1 * v1 : 0.f)
                 + (e0123 ? v0 * v0 : 0.f);

        // leading run (class c0), flushed directly when distinct (~5%)
        float hs = v0 + (h1 ? v1 : 0.f) + (h2 ? v2 : 0.f);
        float hq = v0 * v0 + (h1 ? v1 * v1 : 0.f) + (h2 ? v2 * v2 : 0.f);
        const int hidx = c0 * (B_ * C_) + base;
        if (headp) atomicAdd(&g_sum[hidx], hs);
        if (headp) atomicAdd(&g_sq [hidx], hq);

        // rare middle singleton runs (~0.3%)
        const int m1idx = c1 * (B_ * C_) + base;
        const int m2idx = c2 * (B_ * C_) + base;
        if (m1p) atomicAdd(&g_sum[m1idx], v1);
        if (m1p) atomicAdd(&g_sq [m1idx], v1 * v1);
        if (m2p) atomicAdd(&g_sum[m2idx], v2);
        if (m2p) atomicAdd(&g_sq [m2idx], v2 * v2);

        // warp segmented reduction over per-lane trailing partials
        // (classes non-decreasing across lanes => contiguous segments)
        int cseg = c3;
#pragma unroll
        for (int d = 1; d < 32; d <<= 1) {
            int   oc = __shfl_up_sync(0xffffffffu, cseg, d);
            float os = __shfl_up_sync(0xffffffffu, rs, d);
            float oq = __shfl_up_sync(0xffffffffu, rq, d);
            bool take = (lane >= d) && (oc == cseg);
            rs += take ? os : 0.f;
            rq += take ? oq : 0.f;
        }
        const int nxt = __shfl_down_sync(0xffffffffu, cseg, 1);
        const bool tail = (lane == 31) || (nxt != cseg);
        const int tidx = cseg * (B_ * C_) + base;
        if (tail) atomicAdd(&g_sum[tidx], rs);
        if (tail) atomicAdd(&g_sq [tidx], rq);

        if (more) ((float4*)s_vals[buf ^ 1])[tid] = nv;
        __syncthreads();
    }
}

// =============== kernel 2: finalize affine params + reset accumulators ======
__global__ void __launch_bounds__(C_) k_finalize(const float* __restrict__ emu,
                                                 const float* __restrict__ estd) {
    const int c  = blockIdx.x;     // 0..18
    const int ch = threadIdx.x;    // 0..63

    float mean[B_], sd[B_];
#pragma unroll
    for (int b = 0; b < B_; ++b) {
        int   n   = g_cnt[c * B_ + b];
        float fn  = (n > 0) ? (float)n : 1.f;
        int   idx = (c * B_ + b) * C_ + ch;
        float m   = g_sum[idx] / fn;
        float q   = g_sq[idx]  / fn;
        float var = fmaxf(q - m * m, 0.f);
        mean[b] = m;
        sd[b]   = sqrtf(var + EPS_);
    }
    float am = 0.25f * (mean[0] + mean[1] + mean[2] + mean[3]);
    float as = 0.25f * (sd[0] + sd[1] + sd[2] + sd[3]);
    float vm = 0.f, vs = 0.f;
#pragma unroll
    for (int b = 0; b < B_; ++b) {
        vm += (mean[b] - am) * (mean[b] - am);
        vs += (sd[b]   - as) * (sd[b]   - as);
    }
    vm *= (1.f / 3.f);   // ddof = 1, B = 4
    vs *= (1.f / 3.f);
    float sqm = sqrtf(vm + EPS_);
    float sqs = sqrtf(vs + EPS_);

#pragma unroll
    for (int b = 0; b < B_; ++b) {
        int   idx   = (c * B_ + b) * C_ + ch;
        float beta  = mean[b] + emu[idx]  * sqm;
        float gamma = sd[b]   + estd[idx] * sqs;
        float sc    = gamma / sd[b];
        g_sb[idx] = make_float2(sc, beta - mean[b] * sc);
    }

    // reset accumulators for the next graph replay (deterministic state)
    __syncthreads();
#pragma unroll
    for (int b = 0; b < B_; ++b) {
        int idx = (c * B_ + b) * C_ + ch;
        g_sum[idx] = 0.f;
        g_sq [idx] = 0.f;
    }
    if (ch < B_) g_cnt[c * B_ + ch] = 0;
}

// =============== kernel 3: apply out = x*scale[c] + bias[c] =================
// Table lives in warp registers (lane i holds entry i); lookup via shfl.idx.
__global__ void __launch_bounds__(256) k_apply(const float* __restrict__ x,
                                               float* __restrict__ out) {
    const int bid = blockIdx.x;          // 2048 = (4b*64ch)*8 splits
    const int s   = bid & 7;
    const int bc  = bid >> 3;            // b*64 + ch
    const int ch  = bc & 63;
    const int b   = bc >> 6;
    const int tid  = threadIdx.x;
    const int lane = tid & 31;

    float ssc = 0.f, sbi = 0.f;
    if (lane < NC_) {
        float2 t = g_sb[(lane * B_ + b) * C_ + ch];
        ssc = t.x; sbi = t.y;
    }

    const size_t base = ((size_t)bc) * P_ + s * 4096;
    const float4*   xp = (const float4*)(x + base);
    float4*         op = (float4*)(out + base);
    const unsigned* gp = (const unsigned*)(g_gtr + b * P_ + s * 4096);

#pragma unroll
    for (int j = 0; j < 4; ++j) {
        int i = tid + j * 256;
        float4   v = xp[i];
        unsigned u = gp[i];
        float4 r;
        {
            int c = u & 255u;
            r.x = fmaf(v.x, __shfl_sync(0xffffffffu, ssc, c),
                             __shfl_sync(0xffffffffu, sbi, c));
        }
        {
            int c = (u >> 8) & 255u;
            r.y = fmaf(v.y, __shfl_sync(0xffffffffu, ssc, c),
                             __shfl_sync(0xffffffffu, sbi, c));
        }
        {
            int c = (u >> 16) & 255u;
            r.z = fmaf(v.z, __shfl_sync(0xffffffffu, ssc, c),
                             __shfl_sync(0xffffffffu, sbi, c));
        }
        {
            int c = u >> 24;
            r.w = fmaf(v.w, __shfl_sync(0xffffffffu, ssc, c),
                             __shfl_sync(0xffffffffu, sbi, c));
        }
        op[i] = r;
    }
}

// =============== launch ======================================================
extern "C" void kernel_launch(void* const* d_in, const int* in_sizes, int n_in,
                              void* d_out, int out_size) {
    const float* x    = (const float*)d_in[0];
    const int*   gt   = (const int*)  d_in[1];
    const float* emu  = (const float*)d_in[2];
    const float* estd = (const float*)d_in[3];
    float*       out  = (float*)d_out;

    k_stats   <<<B_ * ST_TILES * 4, ST_THR>>>(x, gt);
    k_finalize<<<NC_, C_>>>(emu, estd);
    k_apply   <<<B_ * C_ * 8, 256>>>(x, out);
}